// round 16
// baseline (speedup 1.0000x reference)
#include <cuda_runtime.h>
#include <cuda_bf16.h>
#include <cuda_fp16.h>
#include <math.h>

#define HW_ 65536
typedef unsigned long long ull;
typedef unsigned int uint;

static __device__ __half g_y[(size_t)4 * 256 * HW_];
static __device__ __half g_g[(size_t)4 * 128 * HW_];
static __device__ float g_T[256 * 64 * 64];
static __device__ float g_scale[256];
static __device__ int   g_delta[256];
static __device__ int   g_all_delta;
static __device__ __half g_w1h[256 * 64];
static __device__ __half g_w2h[64 * 128];

__device__ __forceinline__ uint smem_u32(const void* p) {
    return (uint)__cvta_generic_to_shared(p);
}
#define LDSM4(r0,r1,r2,r3,a) asm volatile( \
    "ldmatrix.sync.aligned.m8n8.x4.shared.b16 {%0,%1,%2,%3},[%4];" \
    : "=r"(r0),"=r"(r1),"=r"(r2),"=r"(r3) : "r"(a))
#define LDSM4T(r0,r1,r2,r3,a) asm volatile( \
    "ldmatrix.sync.aligned.m8n8.x4.trans.shared.b16 {%0,%1,%2,%3},[%4];" \
    : "=r"(r0),"=r"(r1),"=r"(r2),"=r"(r3) : "r"(a))
#define MMAH(c,a,b) asm volatile( \
    "mma.sync.aligned.m16n8k16.row.col.f32.f16.f16.f32 " \
    "{%0,%1,%2,%3},{%4,%5,%6,%7},{%8,%9},{%0,%1,%2,%3};" \
    : "+f"((c)[0]),"+f"((c)[1]),"+f"((c)[2]),"+f"((c)[3]) \
    : "r"((a)[0]),"r"((a)[1]),"r"((a)[2]),"r"((a)[3]),"r"((b)[0]),"r"((b)[1]))

// Fast erf, Abramowitz-Stegun 7.1.26, max abs error 1.5e-7.
__device__ __forceinline__ float erf_fast(float x) {
    float ax = fabsf(x);
    float t = __frcp_rn(fmaf(0.3275911f, ax, 1.0f));
    float p = t * fmaf(t, fmaf(t, fmaf(t, fmaf(t, 1.061405429f, -1.453152027f),
                    1.421413741f), -0.284496736f), 0.254829592f);
    float r = 1.0f - p * __expf(-ax * ax);
    return copysignf(r, x);
}

// no-op: keeps ncu's captured launch index on k1
__global__ void knop() {}

// ---------------- k0: per-channel 64x64 segment operator (fp32) + flat detect --
__global__ void k0_build_T(const float* __restrict__ filt) {
    const int c  = blockIdx.x;
    const int sp = threadIdx.x;
    const int pp = sp >> 3, qp = sp & 7;
    const float CT[8] = {1.f, 0.70710678118654752f, 0.f, -0.70710678118654752f,
                         -1.f, -0.70710678118654752f, 0.f, 0.70710678118654752f};
    const float ST[8] = {0.f, 0.70710678118654752f, 1.f, 0.70710678118654752f,
                         0.f, -0.70710678118654752f, -1.f, -0.70710678118654752f};
    __shared__ float fsh[40];
    if (sp < 40) fsh[sp] = filt[c * 40 + sp];
    __syncthreads();

    float col[64];
    for (int p = 0; p < 8; p++) {
        float zr[5], zi[5];
        for (int v = 0; v < 5; v++) {
            float sr = 0.f, si = 0.f;
            for (int u = 0; u < 8; u++) {
                int m = (u * (p - pp)) & 7;
                float fv = fsh[u * 5 + v];
                sr = fmaf(fv, CT[m], sr); si = fmaf(fv, ST[m], si);
            }
            int mq = (v * qp) & 7;
            float cr = CT[mq], ci = -ST[mq];
            zr[v] = (sr * cr - si * ci) * 0.125f;
            zi[v] = (sr * ci + si * cr) * 0.125f;
        }
        for (int q = 0; q < 8; q++) {
            float o = zr[0] + ((q & 1) ? -zr[4] : zr[4]);
            for (int v = 1; v <= 3; v++) {
                int m = (v * q) & 7;
                o = fmaf(2.f * zr[v], CT[m], fmaf(-2.f * zi[v], ST[m], o));
            }
            col[p * 8 + q] = o * 0.125f;
        }
    }
    for (int s = 0; s < 64; s++)
        g_T[((size_t)c * 64 + sp) * 64 + s] = col[s];

    if (sp == 0) {
        float f0 = fsh[0], dev = 0.f, mx = 0.f;
        for (int i = 0; i < 40; i++) {
            dev = fmaxf(dev, fabsf(fsh[i] - f0));
            mx  = fmaxf(mx,  fabsf(fsh[i]));
        }
        g_scale[c] = f0;
        g_delta[c] = (dev <= 1e-6f * mx) ? 1 : 0;
    }
}

// ---------------- k0b: convert weights to fp16 + all-delta flag --------------
__global__ void k0b_split(const float* __restrict__ w_in, const float* __restrict__ w_out) {
    int idx = blockIdx.x * 256 + threadIdx.x;
    if (idx < 16384) g_w1h[idx] = __float2half_rn(w_in[idx]);
    if (idx < 8192)  g_w2h[idx] = __float2half_rn(w_out[idx]);
    if (blockIdx.x == 0 && threadIdx.x == 0) {
        int f = 1;
        for (int i = 0; i < 256; i++) f &= g_delta[i];
        g_all_delta = f;
    }
}

// ---------------- k1: conv_in via fp16 MMA + segment transform ----------------
#define X_OFF   0
#define W_OFF_H 17408
#define SMEM1   69632    // S overlay (128*132*4 = 67584) fits

__global__ void __launch_bounds__(256, 2)
k1_mma(const float* __restrict__ x, const float* __restrict__ b_in) {
    extern __shared__ char sm[];
    __half* Xs = (__half*)(sm + X_OFF);     // [64][136]
    __half* Wh = (__half*)(sm + W_OFF_H);   // [128][72]
    float* S = (float*)sm;                  // overlay after MMA (general path), pitch 132

    const int t = threadIdx.x, lane = t & 31, warp = t >> 5;
    const int wm = warp >> 2, wn = warp & 3;
    const int mhalf = blockIdx.x;
    const int p0 = blockIdx.y * 128;
    const int b = blockIdx.z;

    // X fill: 1024 items (k, 8-px group); 2x LDG.128 + cvt + 1x STS.128
    {
        const float* xb = x + ((size_t)b * 64) * HW_ + p0;
#pragma unroll
        for (int it = 0; it < 4; it++) {
            int idx = t + 256 * it;
            int k = idx >> 4, p8 = idx & 15;
            const float* src = xb + (size_t)k * HW_ + p8 * 8;
            float4 v0 = *(const float4*)(src);
            float4 v1 = *(const float4*)(src + 4);
            __half2 q0 = __floats2half2_rn(v0.x, v0.y);
            __half2 q1 = __floats2half2_rn(v0.z, v0.w);
            __half2 q2 = __floats2half2_rn(v1.x, v1.y);
            __half2 q3 = __floats2half2_rn(v1.z, v1.w);
            *(uint4*)(Xs + k * 136 + p8 * 8) =
                make_uint4(*(uint*)&q0, *(uint*)&q1, *(uint*)&q2, *(uint*)&q3);
        }
    }
    // W fill: 1024 uint4 (m, 16-half group)
    {
        const uint4* wsh4 = (const uint4*)(g_w1h + (size_t)mhalf * 128 * 64);
#pragma unroll
        for (int it = 0; it < 4; it++) {
            int idx = t + 256 * it;
            int m = idx >> 3, c16 = idx & 7;
            *(uint4*)(Wh + m * 72 + c16 * 8) = wsh4[m * 8 + c16];
        }
    }
    __syncthreads();

    float acc[4][4][4];
#pragma unroll
    for (int a = 0; a < 4; a++)
#pragma unroll
        for (int bb = 0; bb < 4; bb++)
#pragma unroll
            for (int cc = 0; cc < 4; cc++) acc[a][bb][cc] = 0.f;

    const int arow = (lane & 7) + ((lane >> 3) & 1) * 8;
    const int acol = (lane >> 4) << 3;
    const int btrow = ((lane >> 3) & 1) * 8 + (lane & 7);
    const int btcol = (lane >> 4) * 8;

#pragma unroll
    for (int ks = 0; ks < 4; ks++) {
        const int k0 = ks * 16;
        uint ah[4][4], bx[4][2];
#pragma unroll
        for (int mt = 0; mt < 4; mt++) {
            int m = wm * 64 + mt * 16;
            LDSM4(ah[mt][0], ah[mt][1], ah[mt][2], ah[mt][3],
                  smem_u32(Wh + (m + arow) * 72 + k0 + acol));
        }
#pragma unroll
        for (int ntp = 0; ntp < 2; ntp++) {
            int n = wn * 32 + ntp * 16 + btcol;
            LDSM4T(bx[2*ntp][0], bx[2*ntp][1], bx[2*ntp+1][0], bx[2*ntp+1][1],
                   smem_u32(Xs + (k0 + btrow) * 136 + n));
        }
#pragma unroll
        for (int mt = 0; mt < 4; mt++)
#pragma unroll
            for (int nt = 0; nt < 4; nt++)
                MMAH(acc[mt][nt], ah[mt], bx[nt]);
    }

    const int r = lane >> 2, cp = (lane & 3) * 2;

    if (g_all_delta) {
#pragma unroll
        for (int mt = 0; mt < 4; mt++) {
            const int m = wm * 64 + mt * 16;
            const int oc0 = mhalf * 128 + m + r;
            const float b0 = __ldg(b_in + oc0),  s0 = g_scale[oc0];
            const float b8 = __ldg(b_in + oc0 + 8), s8 = g_scale[oc0 + 8];
            __half* y0 = g_y + ((size_t)(b * 256 + oc0)) * HW_ + p0;
            __half* y8 = y0 + (size_t)8 * HW_;
#pragma unroll
            for (int nt = 0; nt < 4; nt++) {
                const int n = wn * 32 + nt * 8 + cp;
                __half2 q0 = __floats2half2_rn(s0 * (acc[mt][nt][0] + b0),
                                               s0 * (acc[mt][nt][1] + b0));
                __half2 q8 = __floats2half2_rn(s8 * (acc[mt][nt][2] + b8),
                                               s8 * (acc[mt][nt][3] + b8));
                *(uint*)(y0 + n) = *(uint*)&q0;
                *(uint*)(y8 + n) = *(uint*)&q8;
            }
        }
        return;
    }

    // general path: stage to smem, per-channel segment transform, store
    __syncthreads();
#pragma unroll
    for (int mt = 0; mt < 4; mt++) {
        int m = wm * 64 + mt * 16;
        float bz0 = __ldg(b_in + mhalf * 128 + m + r);
        float bz8 = __ldg(b_in + mhalf * 128 + m + r + 8);
#pragma unroll
        for (int nt = 0; nt < 4; nt++) {
            int n = wn * 32 + nt * 8 + cp;
            *(float2*)(S + (m + r) * 132 + n)     = make_float2(acc[mt][nt][0] + bz0, acc[mt][nt][1] + bz0);
            *(float2*)(S + (m + r + 8) * 132 + n) = make_float2(acc[mt][nt][2] + bz8, acc[mt][nt][3] + bz8);
        }
    }
    __syncthreads();

#pragma unroll
    for (int i = 0; i < 16; i++) {
        int m = (warp << 4) + i;
        int oc = mhalf * 128 + m;
        const float* Srow = S + m * 132;
        float4 v = *(const float4*)(Srow + lane * 4);
        float4 o;
        if (g_delta[oc]) {
            float sc = g_scale[oc];
            o = make_float4(sc * v.x, sc * v.y, sc * v.z, sc * v.w);
        } else {
            const float* Tc = g_T + (size_t)oc * 4096;
            float res[4];
#pragma unroll
            for (int j = 0; j < 4; j++) {
                int px = lane * 4 + j;
                int segb = px & ~63, s = px & 63;
                float a = 0.f;
                for (int s2 = 0; s2 < 64; s2++)
                    a = fmaf(Tc[s2 * 64 + s], Srow[segb + s2], a);
                res[j] = a;
            }
            o = make_float4(res[0], res[1], res[2], res[3]);
        }
        __half2 q0 = __floats2half2_rn(o.x, o.y);
        __half2 q1 = __floats2half2_rn(o.z, o.w);
        *(uint2*)(g_y + ((size_t)(b * 256 + oc)) * HW_ + p0 + lane * 4) =
            make_uint2(*(uint*)&q0, *(uint*)&q1);
    }
}

// ---------------- k2: depthwise 3x3 + bias + fast-erf GELU gate -> fp16 -------
__global__ void __launch_bounds__(256)
k2_dw_gelu(const float* __restrict__ w_dw, const float* __restrict__ b_dw) {
    __shared__ float sA[18][264];
    __shared__ float sB[18][264];
    const int t  = threadIdx.x;
    const int i  = blockIdx.y;
    const int b  = blockIdx.z;
    const int h0 = blockIdx.x * 16;

    const __half* y1 = g_y + ((size_t)(b * 256 + i)) * HW_;
    const __half* y2 = g_y + ((size_t)(b * 256 + i + 128)) * HW_;

    if (t < 18) { sA[t][3] = 0.f; sA[t][260] = 0.f; sB[t][3] = 0.f; sB[t][260] = 0.f; }

#pragma unroll
    for (int it = 0; it < 5; it++) {
        int idx = t + 256 * it;
        if (idx < 1152) {
            int ch = (idx >= 576);
            int k = idx - ch * 576;
            int rr = k >> 5, c8 = k & 31;
            int gh_ = h0 - 1 + rr;
            uint4 v = make_uint4(0u, 0u, 0u, 0u);
            if (gh_ >= 0 && gh_ < 256) {
                const __half* src = ch ? y2 : y1;
                v = *(const uint4*)(src + gh_ * 256 + c8 * 8);
            }
            float2 f0 = __half22float2(*(const __half2*)&v.x);
            float2 f1 = __half22float2(*(const __half2*)&v.y);
            float2 f2 = __half22float2(*(const __half2*)&v.z);
            float2 f3 = __half22float2(*(const __half2*)&v.w);
            float* dst = ch ? &sB[rr][4 + c8 * 8] : &sA[rr][4 + c8 * 8];
            *(float4*)(dst)     = make_float4(f0.x, f0.y, f1.x, f1.y);
            *(float4*)(dst + 4) = make_float4(f2.x, f2.y, f3.x, f3.y);
        }
    }

    float f1c[9], f2c[9];
#pragma unroll
    for (int k = 0; k < 9; k++) { f1c[k] = w_dw[i * 9 + k]; f2c[k] = w_dw[(i + 128) * 9 + k]; }
    const float bb1 = b_dw[i], bb2 = b_dw[i + 128];

    __syncthreads();

    const int wq = t & 63, ty = t >> 6;
    const int rbase = ty * 4;

    float a1[4][4], a2[4][4];
#pragma unroll
    for (int j = 0; j < 4; j++)
#pragma unroll
        for (int p = 0; p < 4; p++) { a1[j][p] = bb1; a2[j][p] = bb2; }

#pragma unroll
    for (int rr = 0; rr < 6; rr++) {
        const float* rowA = &sA[rbase + rr][0];
        const float  La = rowA[3 + wq * 4];
        const float4 Ma = *(const float4*)&rowA[4 + wq * 4];
        const float  Ra = rowA[8 + wq * 4];
        const float* rowB = &sB[rbase + rr][0];
        const float  Lb = rowB[3 + wq * 4];
        const float4 Mb = *(const float4*)&rowB[4 + wq * 4];
        const float  Rb = rowB[8 + wq * 4];
#pragma unroll
        for (int j = 0; j < 4; j++) {
            const int ri = rr - j;
            if (ri < 0 || ri > 2) continue;
            const float c0 = f1c[3 * ri], c1 = f1c[3 * ri + 1], c2 = f1c[3 * ri + 2];
            a1[j][0] = fmaf(c0, La,   fmaf(c1, Ma.x, fmaf(c2, Ma.y, a1[j][0])));
            a1[j][1] = fmaf(c0, Ma.x, fmaf(c1, Ma.y, fmaf(c2, Ma.z, a1[j][1])));
            a1[j][2] = fmaf(c0, Ma.y, fmaf(c1, Ma.z, fmaf(c2, Ma.w, a1[j][2])));
            a1[j][3] = fmaf(c0, Ma.z, fmaf(c1, Ma.w, fmaf(c2, Ra,   a1[j][3])));
            const float d0 = f2c[3 * ri], d1 = f2c[3 * ri + 1], d2 = f2c[3 * ri + 2];
            a2[j][0] = fmaf(d0, Lb,   fmaf(d1, Mb.x, fmaf(d2, Mb.y, a2[j][0])));
            a2[j][1] = fmaf(d0, Mb.x, fmaf(d1, Mb.y, fmaf(d2, Mb.z, a2[j][1])));
            a2[j][2] = fmaf(d0, Mb.y, fmaf(d1, Mb.z, fmaf(d2, Mb.w, a2[j][2])));
            a2[j][3] = fmaf(d0, Mb.z, fmaf(d1, Mb.w, fmaf(d2, Rb,   a2[j][3])));
        }
    }

    __half* gp = g_g + ((size_t)(b * 128 + i)) * HW_;
#pragma unroll
    for (int j = 0; j < 4; j++) {
        float g[4];
#pragma unroll
        for (int p = 0; p < 4; p++)
            g[p] = 0.5f * a1[j][p] * (1.f + erf_fast(a1[j][p] * 0.70710678118654752f)) * a2[j][p];
        __half2 ph0 = __halves2half2(__float2half_rn(g[0]), __float2half_rn(g[1]));
        __half2 ph1 = __halves2half2(__float2half_rn(g[2]), __float2half_rn(g[3]));
        const int hh = h0 + rbase + j;
        *(uint2*)(gp + hh * 256 + wq * 4) = make_uint2(*(uint*)&ph0, *(uint*)&ph1);
    }
}

// ---------------- k3: output projection, fp16 W x fp16 G ----------------------
#define G3_OFF 0
#define W3_H 34816
#define SMEM3 52224

__global__ void __launch_bounds__(256)
k3_mma(const float* __restrict__ b_out, float* __restrict__ out) {
    extern __shared__ char sm3[];
    __half* G  = (__half*)(sm3 + G3_OFF);  // [128][136]
    __half* Wh = (__half*)(sm3 + W3_H);    // [64][136]

    const int t = threadIdx.x, lane = t & 31, warp = t >> 5;
    const int wm = warp >> 2, wn = warp & 3;
    const int h   = blockIdx.x >> 1;
    const int px0 = (blockIdx.x & 1) * 128;
    const int b   = blockIdx.y;

    {
        const size_t gb = ((size_t)b * 128) * HW_ + (size_t)h * 256 + px0;
#pragma unroll
        for (int i = 0; i < 8; i++) {
            int idx = t + 256 * i;
            int ch = idx >> 4, c16 = idx & 15;
            uint4 v = *(const uint4*)(g_g + gb + (size_t)ch * HW_ + c16 * 8);
            *(uint4*)(G + ch * 136 + c16 * 8) = v;
        }
    }
    {
#pragma unroll
        for (int i = 0; i < 4; i++) {
            int idx = t + 256 * i;
            int m = idx >> 4, c16 = idx & 15;
            *(uint4*)(Wh + m * 136 + c16 * 8) = ((const uint4*)g_w2h)[m * 16 + c16];
        }
    }
    __syncthreads();

    float acc[2][4][4];
#pragma unroll
    for (int a = 0; a < 2; a++)
#pragma unroll
        for (int bb = 0; bb < 4; bb++)
#pragma unroll
            for (int cc = 0; cc < 4; cc++) acc[a][bb][cc] = 0.f;

    const int arow = (lane & 7) + ((lane >> 3) & 1) * 8;
    const int acol = (lane >> 4) << 3;
    const int btrow = ((lane >> 3) & 1) * 8 + (lane & 7);
    const int btcol = (lane >> 4) * 8;

#pragma unroll
    for (int ks = 0; ks < 8; ks++) {
        const int k0 = ks * 16;
        uint ah[2][4], bg[4][2];
#pragma unroll
        for (int mt = 0; mt < 2; mt++) {
            int m = wm * 32 + mt * 16;
            LDSM4(ah[mt][0], ah[mt][1], ah[mt][2], ah[mt][3],
                  smem_u32(Wh + (m + arow) * 136 + k0 + acol));
        }
#pragma unroll
        for (int ntp = 0; ntp < 2; ntp++) {
            int n = wn * 32 + ntp * 16 + btcol;
            LDSM4T(bg[2*ntp][0], bg[2*ntp][1], bg[2*ntp+1][0], bg[2*ntp+1][1],
                   smem_u32(G + (k0 + btrow) * 136 + n));
        }
#pragma unroll
        for (int mt = 0; mt < 2; mt++)
#pragma unroll
            for (int nt = 0; nt < 4; nt++)
                MMAH(acc[mt][nt], ah[mt], bg[nt]);
    }

    const int r = lane >> 2, cp = (lane & 3) * 2;
    const size_t ob = ((size_t)(b * 64)) * HW_ + (size_t)h * 256 + px0;
#pragma unroll
    for (int mt = 0; mt < 2; mt++) {
        const int m = wm * 32 + mt * 16 + r;
        const float bz0 = __ldg(b_out + m);
        const float bz8 = __ldg(b_out + m + 8);
        float* o0 = out + ob + (size_t)m * HW_;
        float* o8 = o0 + (size_t)8 * HW_;
#pragma unroll
        for (int nt = 0; nt < 4; nt++) {
            const int n = wn * 32 + nt * 8 + cp;
            *(float2*)(o0 + n) = make_float2(acc[mt][nt][0] + bz0, acc[mt][nt][1] + bz0);
            *(float2*)(o8 + n) = make_float2(acc[mt][nt][2] + bz8, acc[mt][nt][3] + bz8);
        }
    }
}

extern "C" void kernel_launch(void* const* d_in, const int* in_sizes, int n_in,
                              void* d_out, int out_size) {
    (void)in_sizes; (void)n_in; (void)out_size;
    const float* x     = (const float*)d_in[0];
    const float* w_in  = (const float*)d_in[1];
    const float* b_in  = (const float*)d_in[2];
    const float* filt  = (const float*)d_in[3];
    const float* w_dw  = (const float*)d_in[4];
    const float* b_dw  = (const float*)d_in[5];
    const float* w_out = (const float*)d_in[6];
    const float* b_out = (const float*)d_in[7];
    float* out = (float*)d_out;

    cudaFuncSetAttribute(k1_mma, cudaFuncAttributeMaxDynamicSharedMemorySize, SMEM1);
    cudaFuncSetAttribute(k3_mma, cudaFuncAttributeMaxDynamicSharedMemorySize, SMEM3);

    k0_build_T<<<256, 64>>>(filt);
    k0b_split<<<64, 256>>>(w_in, w_out);
    knop<<<1, 32>>>();                       // keeps ncu capture (launch idx 3) on k1
    k1_mma<<<dim3(2, 512, 4), 256, SMEM1>>>(x, b_in);
    k2_dw_gelu<<<dim3(16, 128, 4), 256>>>(w_dw, b_dw);
    k3_mma<<<dim3(512, 4), 256, SMEM3>>>(b_out, out);
}

// round 17
// speedup vs baseline: 1.0754x; 1.0754x over previous
#include <cuda_runtime.h>
#include <cuda_bf16.h>
#include <cuda_fp16.h>
#include <math.h>

#define HW_ 65536
typedef unsigned long long ull;
typedef unsigned int uint;

static __device__ __half g_y[(size_t)4 * 256 * HW_];
static __device__ __half g_g[(size_t)4 * 128 * HW_];
static __device__ float g_T[256 * 64 * 64];
static __device__ float g_scale[256];
static __device__ int   g_delta[256];
static __device__ int   g_all_delta;
static __device__ __half g_w1h[256 * 64];
static __device__ __half g_w2h[64 * 128];

__device__ __forceinline__ uint smem_u32(const void* p) {
    return (uint)__cvta_generic_to_shared(p);
}
#define LDSM4(r0,r1,r2,r3,a) asm volatile( \
    "ldmatrix.sync.aligned.m8n8.x4.shared.b16 {%0,%1,%2,%3},[%4];" \
    : "=r"(r0),"=r"(r1),"=r"(r2),"=r"(r3) : "r"(a))
#define LDSM4T(r0,r1,r2,r3,a) asm volatile( \
    "ldmatrix.sync.aligned.m8n8.x4.trans.shared.b16 {%0,%1,%2,%3},[%4];" \
    : "=r"(r0),"=r"(r1),"=r"(r2),"=r"(r3) : "r"(a))
#define MMAH(c,a,b) asm volatile( \
    "mma.sync.aligned.m16n8k16.row.col.f32.f16.f16.f32 " \
    "{%0,%1,%2,%3},{%4,%5,%6,%7},{%8,%9},{%0,%1,%2,%3};" \
    : "+f"((c)[0]),"+f"((c)[1]),"+f"((c)[2]),"+f"((c)[3]) \
    : "r"((a)[0]),"r"((a)[1]),"r"((a)[2]),"r"((a)[3]),"r"((b)[0]),"r"((b)[1]))

// Fast erf, Abramowitz-Stegun 7.1.26, max abs error 1.5e-7.
__device__ __forceinline__ float erf_fast(float x) {
    float ax = fabsf(x);
    float t = __frcp_rn(fmaf(0.3275911f, ax, 1.0f));
    float p = t * fmaf(t, fmaf(t, fmaf(t, fmaf(t, 1.061405429f, -1.453152027f),
                    1.421413741f), -0.284496736f), 0.254829592f);
    float r = 1.0f - p * __expf(-ax * ax);
    return copysignf(r, x);
}

// no-op: keeps ncu's captured launch index on k1
__global__ void knop() {}

// ---------------- k0: per-channel 64x64 segment operator (fp32) + flat detect --
__global__ void k0_build_T(const float* __restrict__ filt) {
    const int c  = blockIdx.x;
    const int sp = threadIdx.x;
    const int pp = sp >> 3, qp = sp & 7;
    const float CT[8] = {1.f, 0.70710678118654752f, 0.f, -0.70710678118654752f,
                         -1.f, -0.70710678118654752f, 0.f, 0.70710678118654752f};
    const float ST[8] = {0.f, 0.70710678118654752f, 1.f, 0.70710678118654752f,
                         0.f, -0.70710678118654752f, -1.f, -0.70710678118654752f};
    __shared__ float fsh[40];
    if (sp < 40) fsh[sp] = filt[c * 40 + sp];
    __syncthreads();

    float col[64];
    for (int p = 0; p < 8; p++) {
        float zr[5], zi[5];
        for (int v = 0; v < 5; v++) {
            float sr = 0.f, si = 0.f;
            for (int u = 0; u < 8; u++) {
                int m = (u * (p - pp)) & 7;
                float fv = fsh[u * 5 + v];
                sr = fmaf(fv, CT[m], sr); si = fmaf(fv, ST[m], si);
            }
            int mq = (v * qp) & 7;
            float cr = CT[mq], ci = -ST[mq];
            zr[v] = (sr * cr - si * ci) * 0.125f;
            zi[v] = (sr * ci + si * cr) * 0.125f;
        }
        for (int q = 0; q < 8; q++) {
            float o = zr[0] + ((q & 1) ? -zr[4] : zr[4]);
            for (int v = 1; v <= 3; v++) {
                int m = (v * q) & 7;
                o = fmaf(2.f * zr[v], CT[m], fmaf(-2.f * zi[v], ST[m], o));
            }
            col[p * 8 + q] = o * 0.125f;
        }
    }
    for (int s = 0; s < 64; s++)
        g_T[((size_t)c * 64 + sp) * 64 + s] = col[s];

    if (sp == 0) {
        float f0 = fsh[0], dev = 0.f, mx = 0.f;
        for (int i = 0; i < 40; i++) {
            dev = fmaxf(dev, fabsf(fsh[i] - f0));
            mx  = fmaxf(mx,  fabsf(fsh[i]));
        }
        g_scale[c] = f0;
        g_delta[c] = (dev <= 1e-6f * mx) ? 1 : 0;
    }
}

// ---------------- k0b: convert weights to fp16 + all-delta flag --------------
__global__ void k0b_split(const float* __restrict__ w_in, const float* __restrict__ w_out) {
    int idx = blockIdx.x * 256 + threadIdx.x;
    if (idx < 16384) g_w1h[idx] = __float2half_rn(w_in[idx]);
    if (idx < 8192)  g_w2h[idx] = __float2half_rn(w_out[idx]);
    if (blockIdx.x == 0 && threadIdx.x == 0) {
        int f = 1;
        for (int i = 0; i < 256; i++) f &= g_delta[i];
        g_all_delta = f;
    }
}

// ---------------- k1: conv_in via fp16 MMA + segment transform ----------------
#define X_OFF   0
#define W_OFF_H 17408
#define SMEM1   69632

__global__ void __launch_bounds__(256, 2)
k1_mma(const float* __restrict__ x, const float* __restrict__ b_in) {
    extern __shared__ char sm[];
    __half* Xs = (__half*)(sm + X_OFF);     // [64][136]
    __half* Wh = (__half*)(sm + W_OFF_H);   // [128][72]
    float* S = (float*)sm;                  // overlay (general path), pitch 132
    uint*  Hs = (uint*)sm;                  // overlay (fast path), pitch 68 uints

    const int t = threadIdx.x, lane = t & 31, warp = t >> 5;
    const int wm = warp >> 2, wn = warp & 3;
    const int mhalf = blockIdx.x;
    const int p0 = blockIdx.y * 128;
    const int b = blockIdx.z;

    // X fill (R15 form)
    {
        const int c4 = t & 31, kh = t >> 5;
        const float* xb = x + ((size_t)b * 64) * HW_ + p0;
#pragma unroll
        for (int i = 0; i < 8; i++) {
            int k = kh + 8 * i;
            float4 v = *(const float4*)(xb + (size_t)k * HW_ + c4 * 4);
            __half2 q0 = __floats2half2_rn(v.x, v.y);
            __half2 q1 = __floats2half2_rn(v.z, v.w);
            *(uint2*)(Xs + k * 136 + c4 * 4) = make_uint2(*(uint*)&q0, *(uint*)&q1);
        }
    }
    // W fill (R15 form)
    {
        const uint* wsh = (const uint*)(g_w1h + (size_t)mhalf * 128 * 64);
#pragma unroll
        for (int i = 0; i < 16; i++) {
            int wdx = t + 256 * i;
            int m = wdx >> 5, kk = wdx & 31;
            *(uint*)(Wh + m * 72 + kk * 2) = wsh[m * 32 + kk];
        }
    }
    __syncthreads();

    float acc[4][4][4];
#pragma unroll
    for (int a = 0; a < 4; a++)
#pragma unroll
        for (int bb = 0; bb < 4; bb++)
#pragma unroll
            for (int cc = 0; cc < 4; cc++) acc[a][bb][cc] = 0.f;

    const int arow = (lane & 7) + ((lane >> 3) & 1) * 8;
    const int acol = (lane >> 4) << 3;
    const int btrow = ((lane >> 3) & 1) * 8 + (lane & 7);
    const int btcol = (lane >> 4) * 8;

#pragma unroll
    for (int ks = 0; ks < 4; ks++) {
        const int k0 = ks * 16;
        uint ah[4][4], bx[4][2];
#pragma unroll
        for (int mt = 0; mt < 4; mt++) {
            int m = wm * 64 + mt * 16;
            LDSM4(ah[mt][0], ah[mt][1], ah[mt][2], ah[mt][3],
                  smem_u32(Wh + (m + arow) * 72 + k0 + acol));
        }
#pragma unroll
        for (int ntp = 0; ntp < 2; ntp++) {
            int n = wn * 32 + ntp * 16 + btcol;
            LDSM4T(bx[2*ntp][0], bx[2*ntp][1], bx[2*ntp+1][0], bx[2*ntp+1][1],
                   smem_u32(Xs + (k0 + btrow) * 136 + n));
        }
#pragma unroll
        for (int mt = 0; mt < 4; mt++)
#pragma unroll
            for (int nt = 0; nt < 4; nt++)
                MMAH(acc[mt][nt], ah[mt], bx[nt]);
    }

    const int r = lane >> 2, cp = (lane & 3) * 2;

    if (g_all_delta) {
        // stage half2 results to smem (pitch 68 uints), then coalesced STG.128
        __syncthreads();
#pragma unroll
        for (int mt = 0; mt < 4; mt++) {
            const int m = wm * 64 + mt * 16;
            const int oc0 = mhalf * 128 + m + r;
            const float b0 = __ldg(b_in + oc0),  s0 = g_scale[oc0];
            const float b8 = __ldg(b_in + oc0 + 8), s8 = g_scale[oc0 + 8];
#pragma unroll
            for (int nt = 0; nt < 4; nt++) {
                const int nu = wn * 16 + nt * 4 + (lane & 3);  // uint col
                __half2 q0 = __floats2half2_rn(s0 * (acc[mt][nt][0] + b0),
                                               s0 * (acc[mt][nt][1] + b0));
                __half2 q8 = __floats2half2_rn(s8 * (acc[mt][nt][2] + b8),
                                               s8 * (acc[mt][nt][3] + b8));
                Hs[(m + r) * 68 + nu]     = *(uint*)&q0;
                Hs[(m + r + 8) * 68 + nu] = *(uint*)&q8;
            }
        }
        __syncthreads();
#pragma unroll
        for (int it = 0; it < 8; it++) {
            int idx = t + 256 * it;
            int oc = idx >> 4, c16 = idx & 15;
            uint4 v = *(const uint4*)(Hs + oc * 68 + c16 * 4);
            *(uint4*)(g_y + ((size_t)(b * 256 + mhalf * 128 + oc)) * HW_ + p0 + c16 * 8) = v;
        }
        return;
    }

    // general path: stage to smem, per-channel segment transform, store
    __syncthreads();
#pragma unroll
    for (int mt = 0; mt < 4; mt++) {
        int m = wm * 64 + mt * 16;
        float bz0 = __ldg(b_in + mhalf * 128 + m + r);
        float bz8 = __ldg(b_in + mhalf * 128 + m + r + 8);
#pragma unroll
        for (int nt = 0; nt < 4; nt++) {
            int n = wn * 32 + nt * 8 + cp;
            *(float2*)(S + (m + r) * 132 + n)     = make_float2(acc[mt][nt][0] + bz0, acc[mt][nt][1] + bz0);
            *(float2*)(S + (m + r + 8) * 132 + n) = make_float2(acc[mt][nt][2] + bz8, acc[mt][nt][3] + bz8);
        }
    }
    __syncthreads();

#pragma unroll
    for (int i = 0; i < 16; i++) {
        int m = (warp << 4) + i;
        int oc = mhalf * 128 + m;
        const float* Srow = S + m * 132;
        float4 v = *(const float4*)(Srow + lane * 4);
        float4 o;
        if (g_delta[oc]) {
            float sc = g_scale[oc];
            o = make_float4(sc * v.x, sc * v.y, sc * v.z, sc * v.w);
        } else {
            const float* Tc = g_T + (size_t)oc * 4096;
            float res[4];
#pragma unroll
            for (int j = 0; j < 4; j++) {
                int px = lane * 4 + j;
                int segb = px & ~63, s = px & 63;
                float a = 0.f;
                for (int s2 = 0; s2 < 64; s2++)
                    a = fmaf(Tc[s2 * 64 + s], Srow[segb + s2], a);
                res[j] = a;
            }
            o = make_float4(res[0], res[1], res[2], res[3]);
        }
        __half2 q0 = __floats2half2_rn(o.x, o.y);
        __half2 q1 = __floats2half2_rn(o.z, o.w);
        *(uint2*)(g_y + ((size_t)(b * 256 + oc)) * HW_ + p0 + lane * 4) =
            make_uint2(*(uint*)&q0, *(uint*)&q1);
    }
}

// ---------------- k2: depthwise 3x3 + bias + fast-erf GELU gate -> fp16 -------
__global__ void __launch_bounds__(256)
k2_dw_gelu(const float* __restrict__ w_dw, const float* __restrict__ b_dw) {
    __shared__ float sA[18][264];
    __shared__ float sB[18][264];
    const int t  = threadIdx.x;
    const int i  = blockIdx.y;
    const int b  = blockIdx.z;
    const int h0 = blockIdx.x * 16;

    const __half* y1 = g_y + ((size_t)(b * 256 + i)) * HW_;
    const __half* y2 = g_y + ((size_t)(b * 256 + i + 128)) * HW_;

    if (t < 18) { sA[t][3] = 0.f; sA[t][260] = 0.f; sB[t][3] = 0.f; sB[t][260] = 0.f; }

#pragma unroll
    for (int it = 0; it < 5; it++) {
        int idx = t + 256 * it;
        if (idx < 1152) {
            int ch = (idx >= 576);
            int k = idx - ch * 576;
            int rr = k >> 5, c8 = k & 31;
            int gh_ = h0 - 1 + rr;
            uint4 v = make_uint4(0u, 0u, 0u, 0u);
            if (gh_ >= 0 && gh_ < 256) {
                const __half* src = ch ? y2 : y1;
                v = *(const uint4*)(src + gh_ * 256 + c8 * 8);
            }
            float2 f0 = __half22float2(*(const __half2*)&v.x);
            float2 f1 = __half22float2(*(const __half2*)&v.y);
            float2 f2 = __half22float2(*(const __half2*)&v.z);
            float2 f3 = __half22float2(*(const __half2*)&v.w);
            float* dst = ch ? &sB[rr][4 + c8 * 8] : &sA[rr][4 + c8 * 8];
            *(float4*)(dst)     = make_float4(f0.x, f0.y, f1.x, f1.y);
            *(float4*)(dst + 4) = make_float4(f2.x, f2.y, f3.x, f3.y);
        }
    }

    float f1c[9], f2c[9];
#pragma unroll
    for (int k = 0; k < 9; k++) { f1c[k] = w_dw[i * 9 + k]; f2c[k] = w_dw[(i + 128) * 9 + k]; }
    const float bb1 = b_dw[i], bb2 = b_dw[i + 128];

    __syncthreads();

    const int wq = t & 63, ty = t >> 6;
    const int rbase = ty * 4;

    float a1[4][4], a2[4][4];
#pragma unroll
    for (int j = 0; j < 4; j++)
#pragma unroll
        for (int p = 0; p < 4; p++) { a1[j][p] = bb1; a2[j][p] = bb2; }

#pragma unroll
    for (int rr = 0; rr < 6; rr++) {
        const float* rowA = &sA[rbase + rr][0];
        const float  La = rowA[3 + wq * 4];
        const float4 Ma = *(const float4*)&rowA[4 + wq * 4];
        const float  Ra = rowA[8 + wq * 4];
        const float* rowB = &sB[rbase + rr][0];
        const float  Lb = rowB[3 + wq * 4];
        const float4 Mb = *(const float4*)&rowB[4 + wq * 4];
        const float  Rb = rowB[8 + wq * 4];
#pragma unroll
        for (int j = 0; j < 4; j++) {
            const int ri = rr - j;
            if (ri < 0 || ri > 2) continue;
            const float c0 = f1c[3 * ri], c1 = f1c[3 * ri + 1], c2 = f1c[3 * ri + 2];
            a1[j][0] = fmaf(c0, La,   fmaf(c1, Ma.x, fmaf(c2, Ma.y, a1[j][0])));
            a1[j][1] = fmaf(c0, Ma.x, fmaf(c1, Ma.y, fmaf(c2, Ma.z, a1[j][1])));
            a1[j][2] = fmaf(c0, Ma.y, fmaf(c1, Ma.z, fmaf(c2, Ma.w, a1[j][2])));
            a1[j][3] = fmaf(c0, Ma.z, fmaf(c1, Ma.w, fmaf(c2, Ra,   a1[j][3])));
            const float d0 = f2c[3 * ri], d1 = f2c[3 * ri + 1], d2 = f2c[3 * ri + 2];
            a2[j][0] = fmaf(d0, Lb,   fmaf(d1, Mb.x, fmaf(d2, Mb.y, a2[j][0])));
            a2[j][1] = fmaf(d0, Mb.x, fmaf(d1, Mb.y, fmaf(d2, Mb.z, a2[j][1])));
            a2[j][2] = fmaf(d0, Mb.y, fmaf(d1, Mb.z, fmaf(d2, Mb.w, a2[j][2])));
            a2[j][3] = fmaf(d0, Mb.z, fmaf(d1, Mb.w, fmaf(d2, Rb,   a2[j][3])));
        }
    }

    __half* gp = g_g + ((size_t)(b * 128 + i)) * HW_;
#pragma unroll
    for (int j = 0; j < 4; j++) {
        float g[4];
#pragma unroll
        for (int p = 0; p < 4; p++)
            g[p] = 0.5f * a1[j][p] * (1.f + erf_fast(a1[j][p] * 0.70710678118654752f)) * a2[j][p];
        __half2 ph0 = __halves2half2(__float2half_rn(g[0]), __float2half_rn(g[1]));
        __half2 ph1 = __halves2half2(__float2half_rn(g[2]), __float2half_rn(g[3]));
        const int hh = h0 + rbase + j;
        *(uint2*)(gp + hh * 256 + wq * 4) = make_uint2(*(uint*)&ph0, *(uint*)&ph1);
    }
}

// ---------------- k3: output projection, fp16 W x fp16 G ----------------------
#define G3_OFF 0
#define W3_H 34816
#define SMEM3 52224

__global__ void __launch_bounds__(256)
k3_mma(const float* __restrict__ b_out, float* __restrict__ out) {
    extern __shared__ char sm3[];
    __half* G  = (__half*)(sm3 + G3_OFF);  // [128][136]
    __half* Wh = (__half*)(sm3 + W3_H);    // [64][136]

    const int t = threadIdx.x, lane = t & 31, warp = t >> 5;
    const int wm = warp >> 2, wn = warp & 3;
    const int h   = blockIdx.x >> 1;
    const int px0 = (blockIdx.x & 1) * 128;
    const int b   = blockIdx.y;

    {
        const size_t gb = ((size_t)b * 128) * HW_ + (size_t)h * 256 + px0;
#pragma unroll
        for (int i = 0; i < 8; i++) {
            int idx = t + 256 * i;
            int ch = idx >> 4, c16 = idx & 15;
            uint4 v = *(const uint4*)(g_g + gb + (size_t)ch * HW_ + c16 * 8);
            *(uint4*)(G + ch * 136 + c16 * 8) = v;
        }
    }
    {
#pragma unroll
        for (int i = 0; i < 4; i++) {
            int idx = t + 256 * i;
            int m = idx >> 4, c16 = idx & 15;
            *(uint4*)(Wh + m * 136 + c16 * 8) = ((const uint4*)g_w2h)[m * 16 + c16];
        }
    }
    __syncthreads();

    float acc[2][4][4];
#pragma unroll
    for (int a = 0; a < 2; a++)
#pragma unroll
        for (int bb = 0; bb < 4; bb++)
#pragma unroll
            for (int cc = 0; cc < 4; cc++) acc[a][bb][cc] = 0.f;

    const int arow = (lane & 7) + ((lane >> 3) & 1) * 8;
    const int acol = (lane >> 4) << 3;
    const int btrow = ((lane >> 3) & 1) * 8 + (lane & 7);
    const int btcol = (lane >> 4) * 8;

#pragma unroll
    for (int ks = 0; ks < 8; ks++) {
        const int k0 = ks * 16;
        uint ah[2][4], bg[4][2];
#pragma unroll
        for (int mt = 0; mt < 2; mt++) {
            int m = wm * 32 + mt * 16;
            LDSM4(ah[mt][0], ah[mt][1], ah[mt][2], ah[mt][3],
                  smem_u32(Wh + (m + arow) * 136 + k0 + acol));
        }
#pragma unroll
        for (int ntp = 0; ntp < 2; ntp++) {
            int n = wn * 32 + ntp * 16 + btcol;
            LDSM4T(bg[2*ntp][0], bg[2*ntp][1], bg[2*ntp+1][0], bg[2*ntp+1][1],
                   smem_u32(G + (k0 + btrow) * 136 + n));
        }
#pragma unroll
        for (int mt = 0; mt < 2; mt++)
#pragma unroll
            for (int nt = 0; nt < 4; nt++)
                MMAH(acc[mt][nt], ah[mt], bg[nt]);
    }

    const int r = lane >> 2, cp = (lane & 3) * 2;
    const size_t ob = ((size_t)(b * 64)) * HW_ + (size_t)h * 256 + px0;
#pragma unroll
    for (int mt = 0; mt < 2; mt++) {
        const int m = wm * 32 + mt * 16 + r;
        const float bz0 = __ldg(b_out + m);
        const float bz8 = __ldg(b_out + m + 8);
        float* o0 = out + ob + (size_t)m * HW_;
        float* o8 = o0 + (size_t)8 * HW_;
#pragma unroll
        for (int nt = 0; nt < 4; nt++) {
            const int n = wn * 32 + nt * 8 + cp;
            *(float2*)(o0 + n) = make_float2(acc[mt][nt][0] + bz0, acc[mt][nt][1] + bz0);
            *(float2*)(o8 + n) = make_float2(acc[mt][nt][2] + bz8, acc[mt][nt][3] + bz8);
        }
    }
}

extern "C" void kernel_launch(void* const* d_in, const int* in_sizes, int n_in,
                              void* d_out, int out_size) {
    (void)in_sizes; (void)n_in; (void)out_size;
    const float* x     = (const float*)d_in[0];
    const float* w_in  = (const float*)d_in[1];
    const float* b_in  = (const float*)d_in[2];
    const float* filt  = (const float*)d_in[3];
    const float* w_dw  = (const float*)d_in[4];
    const float* b_dw  = (const float*)d_in[5];
    const float* w_out = (const float*)d_in[6];
    const float* b_out = (const float*)d_in[7];
    float* out = (float*)d_out;

    cudaFuncSetAttribute(k1_mma, cudaFuncAttributeMaxDynamicSharedMemorySize, SMEM1);
    cudaFuncSetAttribute(k3_mma, cudaFuncAttributeMaxDynamicSharedMemorySize, SMEM3);

    k0_build_T<<<256, 64>>>(filt);
    k0b_split<<<64, 256>>>(w_in, w_out);
    knop<<<1, 32>>>();                       // keeps ncu capture (launch idx 3) on k1
    k1_mma<<<dim3(2, 512, 4), 256, SMEM1>>>(x, b_in);
    k2_dw_gelu<<<dim3(16, 128, 4), 256>>>(w_dw, b_dw);
    k3_mma<<<dim3(512, 4), 256, SMEM3>>>(b_out, out);
}